// round 15
// baseline (speedup 1.0000x reference)
#include <cuda_runtime.h>
#include <cstdint>

// Problem constants (fixed by the reference)
#define BB 64
#define TT 2048
#define EE 512
#define RR 1024
#define AA 128
#define HH 8
#define HD 16
#define NF 32
#define KSZ 31
#define PADL 15
#define SCALE 0.25f          // 1/sqrt(16)
#define CSCALE 0.025f        // 0.1 * scale

#define TC 128               // t-rows per scores CTA
#define KC 32                // e-chunk per tile stage
#define NSPLIT (TT / TC)     // 16 t-chunks for context partials

// packed f32x2 helpers (FFMA2 only reachable via PTX)
#define FMA2(acc, a, b) \
    asm("fma.rn.f32x2 %0, %1, %2, %0;" : "+l"(acc) : "l"(a), "l"(b))
#define PACK2(dst, x) \
    asm("mov.b64 %0, {%1, %1};" : "=l"(dst) : "r"(__float_as_uint(x)))
#define UNPACK2(lo, hi, src) \
    asm("mov.b64 {%0, %1}, %2;" : "=r"(lo), "=r"(hi) : "l"(src))

// -------- device scratch (allocation-free rule: __device__ globals) --------
__device__ float g_Qh[BB * AA];                 // [B,H,HD] flattened
__device__ float g_wq[BB * HH * EE];            // effective E-space query per (b,h)
__device__ float g_qbk[BB * HH];                // Qh . bk_h
__device__ float g_cv[BB * HH * 2 * KSZ];       // effective conv filter per (b,h)
__device__ float g_sc[BB * HH * TT];            // scores scratch (16 MB, L2-resident)
__device__ float g_cp[BB * NSPLIT * EE];        // context partials
__device__ float g_M[BB * HH];                  // per-head global max
__device__ float g_iZ[BB * HH];                 // per-head 1/Z

// ============================================================================
// K1: Qh[b,a] = query[b,:] . Wq[a,:] + bq[a]      (one warp per output)
// ============================================================================
__global__ __launch_bounds__(256) void k_qproj(const float* __restrict__ q,
                                               const float* __restrict__ Wq,
                                               const float* __restrict__ bq) {
    int widx = blockIdx.x * 8 + (threadIdx.x >> 5);
    int lane = threadIdx.x & 31;
    int b = widx >> 7;
    int a = widx & 127;
    const float4* qr = (const float4*)(q + (size_t)b * RR);
    const float4* wr = (const float4*)(Wq + (size_t)a * RR);
    float s = 0.f;
#pragma unroll
    for (int it = 0; it < RR / 128; ++it) {
        float4 x = qr[lane + it * 32];
        float4 w = wr[lane + it * 32];
        s += x.x * w.x + x.y * w.y + x.z * w.z + x.w * w.w;
    }
#pragma unroll
    for (int o = 16; o; o >>= 1) s += __shfl_down_sync(0xffffffffu, s, o);
    if (lane == 0) g_Qh[b * AA + a] = s + bq[a];
}

// ============================================================================
// K2: per (b,h) effective query vector / bias / conv filter
// ============================================================================
__global__ __launch_bounds__(64) void k_eff(const float* __restrict__ Wk,
                                            const float* __restrict__ bk,
                                            const float* __restrict__ Wl,
                                            const float* __restrict__ cw) {
    int bh = blockIdx.x;
    int b = bh >> 3, h = bh & 7;
    int tid = threadIdx.x;
    __shared__ float qh[HD];
    __shared__ float wl[NF];
    if (tid < HD) qh[tid] = g_Qh[b * AA + h * HD + tid];
    __syncthreads();

    for (int e = tid; e < EE; e += 64) {
        float s = 0.f;
#pragma unroll
        for (int d = 0; d < HD; ++d) s += qh[d] * Wk[(h * HD + d) * EE + e];
        g_wq[(size_t)bh * EE + e] = s;
    }
    if (tid < NF) {
        float s = 0.f;
#pragma unroll
        for (int d = 0; d < HD; ++d) s += qh[d] * Wl[(h * HD + d) * NF + tid];
        wl[tid] = s;
    }
    if (tid == 0) {
        float s = 0.f;
#pragma unroll
        for (int d = 0; d < HD; ++d) s += qh[d] * bk[h * HD + d];
        g_qbk[bh] = s;
    }
    __syncthreads();
    if (tid < 2 * KSZ) {
        int c = tid / KSZ, k = tid % KSZ;
        float s = 0.f;
#pragma unroll
        for (int f = 0; f < NF; ++f) s += wl[f] * cw[(f * 2 + c) * KSZ + k];
        g_cv[bh * 2 * KSZ + tid] = s;
    }
}

// ============================================================================
// K3: scores — register-double-buffered tile pipeline + f32x2 FMA
// ============================================================================
__global__ __launch_bounds__(128) void k_scores(const float* __restrict__ mem,
                                                const float* __restrict__ aw,
                                                const unsigned char* __restrict__ mask) {
    const int b = blockIdx.y;
    const int t0 = blockIdx.x * TC;
    const int tid = threadIdx.x;

    __shared__ float s_tile[KC][TC + 1];      // 16.5 KB, transposed tile
    __shared__ float s_wq[EE][HH];            // 16 KB   wq_eff as [e][h]
    __shared__ float s_cv[HH][64];            // padded [h][c*32+k]
    __shared__ float s_aw[2][TC + 2 * PADL];
    __shared__ float s_qbk[HH];

    for (int i = tid; i < HH * EE; i += 128) {
        int h = i >> 9, e = i & 511;
        s_wq[e][h] = g_wq[(size_t)(b * HH) * EE + i];
    }
    for (int i = tid; i < HH * 2 * KSZ; i += 128) {
        int h = i / (2 * KSZ), r = i % (2 * KSZ);
        int c = r / KSZ, k = r % KSZ;
        s_cv[h][c * 32 + k] = g_cv[(b * HH + h) * 2 * KSZ + r];
    }
    for (int i = tid; i < 2 * (TC + 2 * PADL); i += 128) {
        int c = i / (TC + 2 * PADL);
        int x = i % (TC + 2 * PADL);
        int gt = t0 - PADL + x;
        s_aw[c][x] = (gt >= 0 && gt < TT) ? aw[((size_t)b * 2 + c) * TT + gt] : 0.f;
    }
    if (tid < HH) s_qbk[tid] = g_qbk[b * HH + tid];

    unsigned long long acc01 = 0ull, acc23 = 0ull, acc45 = 0ull, acc67 = 0ull;

    const float4* gm = (const float4*)mem;
    const size_t rowbase = (size_t)b * TT + t0;
    const int row0 = tid >> 3, j40 = tid & 7;   // per-thread staging coords

    float4 pf[8];                                // prefetch regs: chunk tile slice
#pragma unroll
    for (int k = 0; k < 8; ++k)
        pf[k] = gm[(rowbase + row0 + k * 16) * (EE / 4) + j40];

    for (int kc = 0; kc < EE / KC; ++kc) {       // 16 k-chunks
        __syncthreads();                          // prior compute done
#pragma unroll
        for (int k = 0; k < 8; ++k) {             // transposed STS (conflict-free)
            int row = row0 + k * 16;
            s_tile[j40 * 4 + 0][row] = pf[k].x;
            s_tile[j40 * 4 + 1][row] = pf[k].y;
            s_tile[j40 * 4 + 2][row] = pf[k].z;
            s_tile[j40 * 4 + 3][row] = pf[k].w;
        }
        if (kc + 1 < EE / KC) {                   // overlap next loads w/ compute
#pragma unroll
            for (int k = 0; k < 8; ++k)
                pf[k] = gm[(rowbase + row0 + k * 16) * (EE / 4) + (kc + 1) * 8 + j40];
        }
        __syncthreads();
#pragma unroll
        for (int j = 0; j < KC; ++j) {
            float m = s_tile[j][tid];             // conflict-free column
            unsigned long long mm;
            PACK2(mm, m);
            const ulonglong2* wp = (const ulonglong2*)&s_wq[kc * KC + j][0];
            ulonglong2 wA = wp[0], wB = wp[1];    // LDS.128 broadcast
            FMA2(acc01, mm, wA.x);
            FMA2(acc23, mm, wA.y);
            FMA2(acc45, mm, wB.x);
            FMA2(acc67, mm, wB.y);
        }
    }

    float acc[HH];
    {
        unsigned int lo, hi;
        UNPACK2(lo, hi, acc01); acc[0] = __uint_as_float(lo); acc[1] = __uint_as_float(hi);
        UNPACK2(lo, hi, acc23); acc[2] = __uint_as_float(lo); acc[3] = __uint_as_float(hi);
        UNPACK2(lo, hi, acc45); acc[4] = __uint_as_float(lo); acc[5] = __uint_as_float(hi);
        UNPACK2(lo, hi, acc67); acc[6] = __uint_as_float(lo); acc[7] = __uint_as_float(hi);
    }

    // location term: 62-tap correlation per head
    float cvt[HH];
#pragma unroll
    for (int h = 0; h < HH; ++h) cvt[h] = 0.f;
#pragma unroll
    for (int c = 0; c < 2; ++c) {
        float av[KSZ];
#pragma unroll
        for (int k = 0; k < KSZ; ++k) av[k] = s_aw[c][tid + k];
#pragma unroll
        for (int h = 0; h < HH; ++h) {
            float s = 0.f;
#pragma unroll
            for (int k = 0; k < KSZ; ++k) s += av[k] * s_cv[h][c * 32 + k];
            cvt[h] += s;
        }
    }

    const int t = t0 + tid;
    const bool msk = mask[(size_t)b * TT + t] != 0;
    const float NEG_INF = __int_as_float(0xff800000);
#pragma unroll
    for (int h = 0; h < HH; ++h) {
        float sc = SCALE * (acc[h] + s_qbk[h]) + CSCALE * cvt[h];
        if (msk) sc = NEG_INF;
        g_sc[((size_t)(b * HH + h) << 11) + t] = sc;
    }
}

// ============================================================================
// K4a: per (b,h) softmax stats M, 1/Z  (g_sc is L2-resident)
// ============================================================================
__global__ __launch_bounds__(256) void k_stats() {
    const int b = blockIdx.x;
    const int lane = threadIdx.x & 31, h = threadIdx.x >> 5;
    const float* sc = g_sc + (size_t)(b * HH + h) * TT;
    float m = __int_as_float(0xff800000);
    for (int t = lane; t < TT; t += 32) m = fmaxf(m, sc[t]);
#pragma unroll
    for (int o = 16; o; o >>= 1) m = fmaxf(m, __shfl_xor_sync(0xffffffffu, m, o));
    if (m == __int_as_float(0xff800000)) m = 0.f;
    float z = 0.f;
    for (int t = lane; t < TT; t += 32) z += __expf(sc[t] - m);
#pragma unroll
    for (int o = 16; o; o >>= 1) z += __shfl_xor_sync(0xffffffffu, z, o);
    if (lane == 0) {
        g_M[b * HH + h] = m;
        g_iZ[b * HH + h] = (z > 0.f) ? 1.f / z : 0.f;
    }
}

// ============================================================================
// K4b: final_weights = (1/H) sum_h softmax_h   -> d_out[B*E + b*T + t]
// Grid (4, B) x 256 threads: 256 CTAs (vs 64 before) for occupancy.
// ============================================================================
__global__ __launch_bounds__(256) void k_fw(float* __restrict__ out) {
    const int b = blockIdx.y;
    const int tid = threadIdx.x;
    __shared__ float sM[HH], sIZ[HH];
    if (tid < HH) { sM[tid] = g_M[b * HH + tid]; sIZ[tid] = g_iZ[b * HH + tid]; }
    __syncthreads();
    float mm[HH], iz[HH];
#pragma unroll
    for (int i = 0; i < HH; ++i) { mm[i] = sM[i]; iz[i] = sIZ[i]; }
    const float* scb = g_sc + (size_t)b * HH * TT;
#pragma unroll
    for (int r = 0; r < 2; ++r) {
        int t = blockIdx.x * 512 + r * 256 + tid;
        float fw = 0.f;
#pragma unroll
        for (int h = 0; h < HH; ++h)
            fw += __expf(scb[(size_t)h * TT + t] - mm[h]) * iz[h];
        out[BB * EE + (size_t)b * TT + t] = fw * 0.125f;
    }
}

// ============================================================================
// K5: context partials (float4 streaming): g_cp[b,ch,e] = sum_t fw*mem
// ============================================================================
__global__ __launch_bounds__(128) void k_ctx_part(const float* __restrict__ mem,
                                                  const float* __restrict__ out) {
    const int b = blockIdx.y, ch = blockIdx.x;
    const int tid = threadIdx.x;
    __shared__ float s_fw[TC];
    s_fw[tid] = out[BB * EE + (size_t)b * TT + ch * TC + tid];
    __syncthreads();
    const float4* mb = (const float4*)(mem + ((size_t)b * TT + (size_t)ch * TC) * EE) + tid;
    float4 acc = make_float4(0.f, 0.f, 0.f, 0.f);
#pragma unroll 8
    for (int t = 0; t < TC; ++t) {
        float4 v = mb[(size_t)t * (EE / 4)];
        float f = s_fw[t];
        acc.x += f * v.x; acc.y += f * v.y;
        acc.z += f * v.z; acc.w += f * v.w;
    }
    ((float4*)g_cp)[(size_t)(b * NSPLIT + ch) * (EE / 4) + tid] = acc;
}

// ============================================================================
// K6: reduce partials -> context (float4)
// ============================================================================
__global__ __launch_bounds__(128) void k_ctx_reduce(float* __restrict__ out) {
    const int b = blockIdx.x, e4 = threadIdx.x;
    float4 s = make_float4(0.f, 0.f, 0.f, 0.f);
#pragma unroll
    for (int c = 0; c < NSPLIT; ++c) {
        float4 v = ((const float4*)g_cp)[(size_t)(b * NSPLIT + c) * (EE / 4) + e4];
        s.x += v.x; s.y += v.y; s.z += v.z; s.w += v.w;
    }
    ((float4*)out)[(size_t)b * (EE / 4) + e4] = s;
}

// ============================================================================
extern "C" void kernel_launch(void* const* d_in, const int* in_sizes, int n_in,
                              void* d_out, int out_size) {
    const float*         query  = (const float*)d_in[0];
    const float*         memory = (const float*)d_in[1];
    const float*         aw     = (const float*)d_in[3];
    const unsigned char* mask   = (const unsigned char*)d_in[4];
    const float*         Wq     = (const float*)d_in[5];
    const float*         bq     = (const float*)d_in[6];
    const float*         Wk     = (const float*)d_in[7];
    const float*         bk     = (const float*)d_in[8];
    const float*         cw     = (const float*)d_in[13];
    const float*         Wl     = (const float*)d_in[14];
    float* out = (float*)d_out;  // [B*E context][B*T final_weights]

    k_qproj<<<1024, 256>>>(query, Wq, bq);
    k_eff<<<BB * HH, 64>>>(Wk, bk, Wl, cw);
    k_scores<<<dim3(TT / TC, BB), 128>>>(memory, aw, mask);
    k_stats<<<BB, 256>>>();
    k_fw<<<dim3(4, BB), 256>>>(out);
    k_ctx_part<<<dim3(NSPLIT, BB), 128>>>(memory, out);
    k_ctx_reduce<<<BB, 128>>>(out);
}

// round 16
// speedup vs baseline: 1.0178x; 1.0178x over previous
#include <cuda_runtime.h>
#include <cstdint>

// Problem constants (fixed by the reference)
#define BB 64
#define TT 2048
#define EE 512
#define RR 1024
#define AA 128
#define HH 8
#define HD 16
#define NF 32
#define KSZ 31
#define PADL 15
#define SCALE 0.25f          // 1/sqrt(16)
#define CSCALE 0.025f        // 0.1 * scale

#define TC 256               // t-rows per scores CTA (grid 8 x 64 = 512 -> 1 wave)
#define KC 32                // e-chunk per tile stage
#define TSTR 36              // tile row stride (floats): 144B, 16B-aligned, LDS.128 conflict-free
#define CTC 128              // ctx chunk rows
#define NSPLIT (TT / CTC)    // 16

// packed f32x2 helpers (FFMA2 only reachable via PTX)
#define FMA2(acc, a, b) \
    asm("fma.rn.f32x2 %0, %1, %2, %0;" : "+l"(acc) : "l"(a), "l"(b))
#define PACK2(dst, x) \
    asm("mov.b64 %0, {%1, %1};" : "=l"(dst) : "r"(__float_as_uint(x)))
#define UNPACK2(lo, hi, src) \
    asm("mov.b64 {%0, %1}, %2;" : "=r"(lo), "=r"(hi) : "l"(src))

#define CP_ASYNC16(dst_u32, src_ptr) \
    asm volatile("cp.async.cg.shared.global [%0], [%1], 16;" :: "r"(dst_u32), "l"(src_ptr))
#define CP_COMMIT() asm volatile("cp.async.commit_group;")
#define CP_WAIT0()  asm volatile("cp.async.wait_group 0;" ::: "memory")

// -------- device scratch (allocation-free rule: __device__ globals) --------
__device__ float g_Qh[BB * AA];
__device__ float g_wq[BB * HH * EE];
__device__ float g_qbk[BB * HH];
__device__ float g_cv[BB * HH * 2 * KSZ];
__device__ float g_sc[BB * HH * TT];            // scores (16 MB, L2-resident)
__device__ float g_cp[BB * NSPLIT * EE];
__device__ float g_Z[BB * HH];                  // per-head exp-sum (no-max softmax)

// ============================================================================
// K1: Qh[b,a] = query[b,:] . Wq[a,:] + bq[a]
// ============================================================================
__global__ __launch_bounds__(256) void k_qproj(const float* __restrict__ q,
                                               const float* __restrict__ Wq,
                                               const float* __restrict__ bq) {
    int widx = blockIdx.x * 8 + (threadIdx.x >> 5);
    int lane = threadIdx.x & 31;
    int b = widx >> 7;
    int a = widx & 127;
    const float4* qr = (const float4*)(q + (size_t)b * RR);
    const float4* wr = (const float4*)(Wq + (size_t)a * RR);
    float s = 0.f;
#pragma unroll
    for (int it = 0; it < RR / 128; ++it) {
        float4 x = qr[lane + it * 32];
        float4 w = wr[lane + it * 32];
        s += x.x * w.x + x.y * w.y + x.z * w.z + x.w * w.w;
    }
#pragma unroll
    for (int o = 16; o; o >>= 1) s += __shfl_down_sync(0xffffffffu, s, o);
    if (lane == 0) g_Qh[b * AA + a] = s + bq[a];
}

// ============================================================================
// K2: per (b,h) effective query vector / bias / conv filter; zeroes g_Z
// ============================================================================
__global__ __launch_bounds__(64) void k_eff(const float* __restrict__ Wk,
                                            const float* __restrict__ bk,
                                            const float* __restrict__ Wl,
                                            const float* __restrict__ cw) {
    int bh = blockIdx.x;
    int b = bh >> 3, h = bh & 7;
    int tid = threadIdx.x;
    __shared__ float qh[HD];
    __shared__ float wl[NF];
    if (tid < HD) qh[tid] = g_Qh[b * AA + h * HD + tid];
    __syncthreads();

    for (int e = tid; e < EE; e += 64) {
        float s = 0.f;
#pragma unroll
        for (int d = 0; d < HD; ++d) s += qh[d] * Wk[(h * HD + d) * EE + e];
        g_wq[(size_t)bh * EE + e] = s;
    }
    if (tid < NF) {
        float s = 0.f;
#pragma unroll
        for (int d = 0; d < HD; ++d) s += qh[d] * Wl[(h * HD + d) * NF + tid];
        wl[tid] = s;
    }
    if (tid == 0) {
        float s = 0.f;
#pragma unroll
        for (int d = 0; d < HD; ++d) s += qh[d] * bk[h * HD + d];
        g_qbk[bh] = s;
        g_Z[bh] = 0.f;                           // zero the atomic accumulator
    }
    __syncthreads();
    if (tid < 2 * KSZ) {
        int c = tid / KSZ, k = tid % KSZ;
        float s = 0.f;
#pragma unroll
        for (int f = 0; f < NF; ++f) s += wl[f] * cw[(f * 2 + c) * KSZ + k];
        g_cv[bh * 2 * KSZ + tid] = s;
    }
}

// ============================================================================
// K3: scores — TC=256, 1 wave, cp.async staging, f32x2 FMA, fused Z epilogue
// ============================================================================
__global__ __launch_bounds__(256, 4) void k_scores(const float* __restrict__ mem,
                                                   const float* __restrict__ aw,
                                                   const unsigned char* __restrict__ mask) {
    const int b = blockIdx.y;
    const int t0 = blockIdx.x * TC;
    const int tid = threadIdx.x;
    const int lane = tid & 31, wid = tid >> 5;

    __shared__ __align__(16) float s_tile[TC][TSTR];   // 36.9 KB (prolog overlays it)
    __shared__ float s_wq[EE][HH];                     // 16 KB  wq_eff as [e][h]
    __shared__ float s_qbk[HH];
    __shared__ float s_z[8][9];                        // Z block-reduce scratch

    // ---- prolog: stage aw + conv filters into (dead) tile region, stage wq ----
    float* s_awF = &s_tile[0][0];                      // [2][TC+30] = 572 floats
    float* s_cvF = s_awF + 2 * (TC + 2 * PADL);        // [8][64]

    for (int i = tid; i < HH * EE; i += 256) {         // wq transpose stage
        int h = i >> 9, e = i & 511;
        s_wq[e][h] = g_wq[(size_t)(b * HH) * EE + i];
    }
    for (int i = tid; i < 2 * (TC + 2 * PADL); i += 256) {
        int c = i / (TC + 2 * PADL);
        int x = i % (TC + 2 * PADL);
        int gt = t0 - PADL + x;
        s_awF[i] = (gt >= 0 && gt < TT) ? aw[((size_t)b * 2 + c) * TT + gt] : 0.f;
    }
    for (int i = tid; i < HH * 2 * KSZ; i += 256) {
        int h = i / (2 * KSZ), r = i % (2 * KSZ);
        int c = r / KSZ, k = r % KSZ;
        s_cvF[h * 64 + c * 32 + k] = g_cv[(b * HH + h) * 2 * KSZ + r];
    }
    if (tid < HH) s_qbk[tid] = g_qbk[b * HH + tid];
    __syncthreads();

    // location term into registers (so tile region can be reused)
    float cvt[HH];
#pragma unroll
    for (int h = 0; h < HH; ++h) cvt[h] = 0.f;
#pragma unroll
    for (int c = 0; c < 2; ++c) {
        float av[KSZ];
#pragma unroll
        for (int k = 0; k < KSZ; ++k) av[k] = s_awF[c * (TC + 2 * PADL) + tid + k];
#pragma unroll
        for (int h = 0; h < HH; ++h) {
            float s = 0.f;
#pragma unroll
            for (int k = 0; k < KSZ; ++k) s += av[k] * s_cvF[h * 64 + c * 32 + k];
            cvt[h] += s;
        }
    }
    float qbk[HH];
#pragma unroll
    for (int h = 0; h < HH; ++h) qbk[h] = s_qbk[h];

    // ---- main loop: stream memory tile, accumulate 8-head dot products ----
    unsigned long long acc01 = 0ull, acc23 = 0ull, acc45 = 0ull, acc67 = 0ull;
    const float* gb = mem + ((size_t)b * TT + t0) * EE;
    uint32_t tile_u32 = (uint32_t)__cvta_generic_to_shared(&s_tile[0][0]);

    for (int kc = 0; kc < EE / KC; ++kc) {            // 16 chunks
        __syncthreads();                               // tile free to overwrite
#pragma unroll
        for (int k = 0; k < 8; ++k) {                  // 2048 x 16B per chunk
            int seg = tid + k * 256;
            int row = seg >> 3, c16 = seg & 7;
            uint32_t d = tile_u32 + (uint32_t)(row * (TSTR * 4) + c16 * 16);
            const float* s = gb + (size_t)row * EE + kc * KC + c16 * 4;
            CP_ASYNC16(d, s);
        }
        CP_COMMIT();
        CP_WAIT0();
        __syncthreads();
#pragma unroll
        for (int jv = 0; jv < KC / 4; ++jv) {          // 8 vector m-loads
            float4 m4 = *(const float4*)&s_tile[tid][jv * 4];
#pragma unroll
            for (int c = 0; c < 4; ++c) {
                int j = kc * KC + jv * 4 + c;
                const ulonglong2* wp = (const ulonglong2*)&s_wq[j][0];
                ulonglong2 wA = wp[0], wB = wp[1];     // 8 head weights (broadcast)
                unsigned long long mm;
                PACK2(mm, (&m4.x)[c]);
                FMA2(acc01, mm, wA.x);
                FMA2(acc23, mm, wA.y);
                FMA2(acc45, mm, wB.x);
                FMA2(acc67, mm, wB.y);
            }
        }
    }

    float acc[HH];
    {
        unsigned int lo, hi;
        UNPACK2(lo, hi, acc01); acc[0] = __uint_as_float(lo); acc[1] = __uint_as_float(hi);
        UNPACK2(lo, hi, acc23); acc[2] = __uint_as_float(lo); acc[3] = __uint_as_float(hi);
        UNPACK2(lo, hi, acc45); acc[4] = __uint_as_float(lo); acc[5] = __uint_as_float(hi);
        UNPACK2(lo, hi, acc67); acc[6] = __uint_as_float(lo); acc[7] = __uint_as_float(hi);
    }

    // ---- epilogue: scores out + fused per-head exp-sum (no-max softmax) ----
    const int t = t0 + tid;
    const bool msk = mask[(size_t)b * TT + t] != 0;
    const float NEG_INF = __int_as_float(0xff800000);
    float eh[HH];
#pragma unroll
    for (int h = 0; h < HH; ++h) {
        float sc = SCALE * (acc[h] + qbk[h]) + CSCALE * cvt[h];
        if (msk) sc = NEG_INF;
        g_sc[((size_t)(b * HH + h) << 11) + t] = sc;
        eh[h] = __expf(sc);                        // exp(-inf)=0 handles mask
    }
#pragma unroll
    for (int h = 0; h < HH; ++h) {
#pragma unroll
        for (int o = 16; o; o >>= 1) eh[h] += __shfl_xor_sync(0xffffffffu, eh[h], o);
    }
    if (lane == 0) {
#pragma unroll
        for (int h = 0; h < HH; ++h) s_z[wid][h] = eh[h];
    }
    __syncthreads();
    if (tid < HH) {
        float z = 0.f;
#pragma unroll
        for (int w = 0; w < 8; ++w) z += s_z[w][tid];
        atomicAdd(&g_Z[b * HH + tid], z);
    }
}

// ============================================================================
// K4: final_weights = (1/H) sum_h exp(sc_h)/Z_h   -> d_out[B*E + b*T + t]
// ============================================================================
__global__ __launch_bounds__(256) void k_fw(float* __restrict__ out) {
    const int b = blockIdx.y;
    const int tid = threadIdx.x;
    __shared__ float sIZ[HH];
    if (tid < HH) {
        float z = g_Z[b * HH + tid];
        sIZ[tid] = (z > 0.f) ? 1.f / z : 0.f;
    }
    __syncthreads();
    float iz[HH];
#pragma unroll
    for (int i = 0; i < HH; ++i) iz[i] = sIZ[i];
    const float* scb = g_sc + (size_t)b * HH * TT;
#pragma unroll
    for (int r = 0; r < 2; ++r) {
        int t = blockIdx.x * 512 + r * 256 + tid;
        float fw = 0.f;
#pragma unroll
        for (int h = 0; h < HH; ++h)
            fw += __expf(scb[(size_t)h * TT + t]) * iz[h];
        out[BB * EE + (size_t)b * TT + t] = fw * 0.125f;
    }
}

// ============================================================================
// K5: context partials, REVERSED iteration order (tail of memory is L2-hot
// from k_scores): g_cp[b,ch,e] = sum_t fw[b,t]*mem[b,t,e]
// ============================================================================
__global__ __launch_bounds__(128) void k_ctx_part(const float* __restrict__ mem,
                                                  const float* __restrict__ out) {
    const int b = BB - 1 - blockIdx.y;
    const int ch = NSPLIT - 1 - blockIdx.x;
    const int tid = threadIdx.x;
    __shared__ float s_fw[CTC];
    s_fw[tid] = out[BB * EE + (size_t)b * TT + ch * CTC + tid];
    __syncthreads();
    const float4* mb = (const float4*)(mem + ((size_t)b * TT + (size_t)ch * CTC) * EE) + tid;
    float4 acc = make_float4(0.f, 0.f, 0.f, 0.f);
#pragma unroll 8
    for (int t = 0; t < CTC; ++t) {
        float4 v = mb[(size_t)t * (EE / 4)];
        float f = s_fw[t];
        acc.x += f * v.x; acc.y += f * v.y;
        acc.z += f * v.z; acc.w += f * v.w;
    }
    ((float4*)g_cp)[(size_t)(b * NSPLIT + ch) * (EE / 4) + tid] = acc;
}

// ============================================================================
// K6: reduce partials -> context (float4)
// ============================================================================
__global__ __launch_bounds__(128) void k_ctx_reduce(float* __restrict__ out) {
    const int b = blockIdx.x, e4 = threadIdx.x;
    float4 s = make_float4(0.f, 0.f, 0.f, 0.f);
#pragma unroll
    for (int c = 0; c < NSPLIT; ++c) {
        float4 v = ((const float4*)g_cp)[(size_t)(b * NSPLIT + c) * (EE / 4) + e4];
        s.x += v.x; s.y += v.y; s.z += v.z; s.w += v.w;
    }
    ((float4*)out)[(size_t)b * (EE / 4) + e4] = s;
}

// ============================================================================
extern "C" void kernel_launch(void* const* d_in, const int* in_sizes, int n_in,
                              void* d_out, int out_size) {
    const float*         query  = (const float*)d_in[0];
    const float*         memory = (const float*)d_in[1];
    const float*         aw     = (const float*)d_in[3];
    const unsigned char* mask   = (const unsigned char*)d_in[4];
    const float*         Wq     = (const float*)d_in[5];
    const float*         bq     = (const float*)d_in[6];
    const float*         Wk     = (const float*)d_in[7];
    const float*         bk     = (const float*)d_in[8];
    const float*         cw     = (const float*)d_in[13];
    const float*         Wl     = (const float*)d_in[14];
    float* out = (float*)d_out;  // [B*E context][B*T final_weights]

    k_qproj<<<1024, 256>>>(query, Wq, bq);
    k_eff<<<BB * HH, 64>>>(Wk, bk, Wl, cw);
    k_scores<<<dim3(TT / TC, BB), 256>>>(memory, aw, mask);
    k_fw<<<dim3(4, BB), 256>>>(out);
    k_ctx_part<<<dim3(NSPLIT, BB), 128>>>(memory, out);
    k_ctx_reduce<<<BB, 128>>>(out);
}